// round 2
// baseline (speedup 1.0000x reference)
#include <cuda_runtime.h>

#define NG   2048
#define NB   4
#define CIN  16
#define COUT 32
#define NCTX 256
#define NOUT 1024

#define TPB  256
#define HALF (NG / 2)          // grid points per block
#define PAD  20                // floats per grid point in smem (16 + 4 pad, conflict-free LDS.128)
#define TGT  4                 // targets per warp
#define TGT_BLK (8 * TGT)      // 32 targets per block

__device__ float g_xmin;
__device__ float g_step;
__device__ float g_sq[CIN];    // sqrt(0.5*log2e)/sigma_c  (exp2 prescale)
__device__ int   g_uniform;
__device__ float g_part[2 * NB * NOUT * COUT];   // per-half projected partials (1 MB scratch)

__device__ __forceinline__ float ex2(float x) {
    float y;
    asm("ex2.approx.ftz.f32 %0, %1;" : "=f"(y) : "f"(x));
    return y;
}
__device__ __forceinline__ unsigned long long pack2(float lo, float hi) {
    unsigned long long v;
    asm("mov.b64 %0, {%1, %2};" : "=l"(v) : "f"(lo), "f"(hi));
    return v;
}
__device__ __forceinline__ void unpack2(unsigned long long v, float& lo, float& hi) {
    asm("mov.b64 {%0, %1}, %2;" : "=f"(lo), "=f"(hi) : "l"(v));
}
__device__ __forceinline__ void fma2(unsigned long long& d, unsigned long long a, unsigned long long b) {
    asm("fma.rn.f32x2 %0, %1, %2, %0;" : "+l"(d) : "l"(a), "l"(b));
}
__device__ __forceinline__ void add2(unsigned long long& d, unsigned long long a) {
    asm("add.rn.f32x2 %0, %0, %1;" : "+l"(d) : "l"(a));
}

// ---------------------------------------------------------------------------
// Prep: min/max over x_context & x_target, exp2 prescales, uniformity flag.
// ---------------------------------------------------------------------------
__global__ void prep_kernel(const float* __restrict__ xc,
                            const float* __restrict__ xt,
                            const float* __restrict__ sigma) {
    __shared__ float smin[TPB];
    __shared__ float smax[TPB];
    __shared__ float sq_s[CIN];
    int tid = threadIdx.x;

    float mn = 1e30f, mx = -1e30f;
    for (int i = tid; i < NB * NCTX; i += TPB) {
        float v = xc[i]; mn = fminf(mn, v); mx = fmaxf(mx, v);
    }
    for (int i = tid; i < NB * NOUT; i += TPB) {
        float v = xt[i]; mn = fminf(mn, v); mx = fmaxf(mx, v);
    }
    smin[tid] = mn; smax[tid] = mx;

    if (tid < CIN) {
        // exp(-0.5 d^2 / s^2) = exp2(-(d*sq)^2), sq = sqrt(0.5*log2(e))/s
        sq_s[tid] = 0.84932180028801907f * expf(-sigma[tid]);
    }
    __syncthreads();

    for (int s = TPB / 2; s > 0; s >>= 1) {
        if (tid < s) {
            smin[tid] = fminf(smin[tid], smin[tid + s]);
            smax[tid] = fmaxf(smax[tid], smax[tid + s]);
        }
        __syncthreads();
    }

    if (tid == 0) {
        float xmin = smin[0] - 0.1f;
        float xmax = smax[0] + 0.1f;
        g_xmin = xmin;
        g_step = (xmax - xmin) / (float)(NG - 1);
        int u = 1;
        #pragma unroll
        for (int c = 1; c < CIN; c++) u &= (sq_s[c] == sq_s[0]) ? 1 : 0;
        g_uniform = u;
    }
    if (tid < CIN) g_sq[tid] = sq_s[tid];
}

// ---------------------------------------------------------------------------
// Main: block = (target-tile, batch, grid-half). r half staged grid-major
// padded in smem; f32x2 packed FMAs; projected partial written to g_part.
// ---------------------------------------------------------------------------
extern __shared__ float s_buf[];

__global__ __launch_bounds__(TPB, 2)
void conv_half_kernel(const float* __restrict__ r,
                      const float* __restrict__ xt,
                      const float* __restrict__ W) {
    float* r_s = s_buf;                   // HALF * PAD
    float* W_s = s_buf + HALF * PAD;      // CIN * COUT

    const int b    = blockIdx.y;
    const int half = blockIdx.z;
    const int tid  = threadIdx.x;
    const int warp = tid >> 5;
    const int lane = tid & 31;

    // Stage this half of r[b]: global [c][NG] -> smem [g][c] (pad 20).
    {
        const float* rb = r + (size_t)b * CIN * NG + half * HALF;
        for (int idx = tid; idx < CIN * HALF; idx += TPB) {
            int c = idx >> 10;            // HALF == 1024
            int g = idx & (HALF - 1);
            r_s[g * PAD + c] = rb[c * NG + g];
        }
    }
    for (int i = tid; i < CIN * COUT; i += TPB) W_s[i] = W[i];
    __syncthreads();

    const int o0 = blockIdx.x * TGT_BLK + warp * TGT;
    float* part = g_part + (size_t)half * (NB * NOUT * COUT)
                         + (size_t)(b * NOUT + o0) * COUT + lane;

    if (g_uniform) {
        const float sq    = g_sq[0];
        const float stepq = g_step * sq;
        const float baseq = fmaf((float)(half * HALF), stepq, g_xmin * sq);

        float xq[TGT];
        #pragma unroll
        for (int t = 0; t < TGT; t++) xq[t] = xt[b * NOUT + o0 + t] * sq;

        unsigned long long acc[TGT][CIN / 2];
        #pragma unroll
        for (int t = 0; t < TGT; t++)
            #pragma unroll
            for (int k = 0; k < CIN / 2; k++) acc[t][k] = 0ull;

        for (int i = lane; i < HALF; i += 32) {
            float gq = fmaf((float)i, stepq, baseq);
            unsigned long long w2[TGT];
            #pragma unroll
            for (int t = 0; t < TGT; t++) {
                float d = gq - xq[t];
                float w = ex2(d * -d);
                w2[t] = pack2(w, w);
            }
            unsigned int a = (unsigned int)__cvta_generic_to_shared(r_s + i * PAD);
            #pragma unroll
            for (int g4 = 0; g4 < 4; g4++) {
                unsigned long long r0, r1;
                asm("ld.shared.v2.u64 {%0, %1}, [%2];"
                    : "=l"(r0), "=l"(r1) : "r"(a + g4 * 16));
                #pragma unroll
                for (int t = 0; t < TGT; t++) {
                    fma2(acc[t][2 * g4 + 0], r0, w2[t]);
                    fma2(acc[t][2 * g4 + 1], r1, w2[t]);
                }
            }
        }

        // Packed butterfly reduction across lanes.
        #pragma unroll
        for (int s = 16; s > 0; s >>= 1) {
            #pragma unroll
            for (int t = 0; t < TGT; t++)
                #pragma unroll
                for (int k = 0; k < CIN / 2; k++) {
                    unsigned long long o = __shfl_xor_sync(0xFFFFFFFFu, acc[t][k], s);
                    add2(acc[t][k], o);
                }
        }

        // Fused projection: lane = output channel. No bias here (combine adds it).
        #pragma unroll
        for (int t = 0; t < TGT; t++) {
            float o = 0.0f;
            #pragma unroll
            for (int k = 0; k < CIN / 2; k++) {
                float lo, hi;
                unpack2(acc[t][k], lo, hi);
                o = fmaf(lo, W_s[(2 * k + 0) * COUT + lane], o);
                o = fmaf(hi, W_s[(2 * k + 1) * COUT + lane], o);
            }
            part[(size_t)t * COUT] = o;
        }
    } else {
        // General per-channel length scales (cold path, scalar).
        float kneg[CIN];
        #pragma unroll
        for (int c = 0; c < CIN; c++) { float s = g_sq[c]; kneg[c] = -(s * s); }

        const float step = g_step;
        const float base = fmaf((float)(half * HALF), step, g_xmin);
        float xv[TGT];
        #pragma unroll
        for (int t = 0; t < TGT; t++) xv[t] = xt[b * NOUT + o0 + t];

        float acc[TGT][CIN];
        #pragma unroll
        for (int t = 0; t < TGT; t++)
            #pragma unroll
            for (int c = 0; c < CIN; c++) acc[t][c] = 0.0f;

        for (int i = lane; i < HALF; i += 32) {
            float gv = fmaf((float)i, step, base);
            #pragma unroll
            for (int t = 0; t < TGT; t++) {
                float d = gv - xv[t];
                float d2 = d * d;
                #pragma unroll
                for (int c = 0; c < CIN; c++)
                    acc[t][c] = fmaf(r_s[i * PAD + c], ex2(d2 * kneg[c]), acc[t][c]);
            }
        }
        #pragma unroll
        for (int s = 16; s > 0; s >>= 1)
            #pragma unroll
            for (int t = 0; t < TGT; t++)
                #pragma unroll
                for (int c = 0; c < CIN; c++)
                    acc[t][c] += __shfl_xor_sync(0xFFFFFFFFu, acc[t][c], s);
        #pragma unroll
        for (int t = 0; t < TGT; t++) {
            float o = 0.0f;
            #pragma unroll
            for (int c = 0; c < CIN; c++)
                o = fmaf(acc[t][c], W_s[c * COUT + lane], o);
            part[(size_t)t * COUT] = o;
        }
    }
}

// ---------------------------------------------------------------------------
// Combine: out = part_half0 + part_half1 + bias. Deterministic (no atomics).
// ---------------------------------------------------------------------------
__global__ void combine_kernel(const float* __restrict__ bias,
                               float* __restrict__ out) {
    int i = blockIdx.x * blockDim.x + threadIdx.x;   // exactly NB*NOUT*COUT threads
    out[i] = g_part[i] + g_part[NB * NOUT * COUT + i] + bias[i & (COUT - 1)];
}

extern "C" void kernel_launch(void* const* d_in, const int* in_sizes, int n_in,
                              void* d_out, int out_size) {
    const float* r     = (const float*)d_in[0];
    const float* xc    = (const float*)d_in[1];
    // d_in[2] = y_context — unused by the reference computation.
    const float* xt    = (const float*)d_in[3];
    const float* sigma = (const float*)d_in[4];
    const float* W     = (const float*)d_in[5];
    const float* bias  = (const float*)d_in[6];
    float* out = (float*)d_out;

    (void)in_sizes; (void)n_in; (void)out_size;

    const int smem_bytes = (HALF * PAD + CIN * COUT) * (int)sizeof(float);
    cudaFuncSetAttribute(conv_half_kernel,
                         cudaFuncAttributeMaxDynamicSharedMemorySize, smem_bytes);

    prep_kernel<<<1, TPB>>>(xc, xt, sigma);
    dim3 grid(NOUT / TGT_BLK, NB, 2);    // (32, 4, 2) = 256 blocks
    conv_half_kernel<<<grid, TPB, smem_bytes>>>(r, xt, W);
    combine_kernel<<<(NB * NOUT * COUT) / TPB, TPB>>>(bias, out);
}

// round 3
// speedup vs baseline: 1.2757x; 1.2757x over previous
#include <cuda_runtime.h>

#define NG   2048
#define NB   4
#define CIN  16
#define COUT 32
#define NCTX 256
#define NOUT 1024

#define TPB  256
#define NWARP 8
#define TGT  4                   // targets per warp
#define TGT_BLK (NWARP * TGT)    // 32 targets per block
#define KP   (CIN / 2)           // 8 channel pairs

__device__ __forceinline__ float ex2(float x) {
    float y;
    asm("ex2.approx.ftz.f32 %0, %1;" : "=f"(y) : "f"(x));
    return y;
}
__device__ __forceinline__ unsigned long long pack2(float lo, float hi) {
    unsigned long long v;
    asm("mov.b64 %0, {%1, %2};" : "=l"(v) : "f"(lo), "f"(hi));
    return v;
}
__device__ __forceinline__ void unpack2(unsigned long long v, float& lo, float& hi) {
    asm("mov.b64 {%0, %1}, %2;" : "=f"(lo), "=f"(hi) : "l"(v));
}
__device__ __forceinline__ void fma2(unsigned long long& d, unsigned long long a, unsigned long long b) {
    asm("fma.rn.f32x2 %0, %1, %2, %0;" : "+l"(d) : "l"(a), "l"(b));
}
__device__ __forceinline__ void add2(unsigned long long& d, unsigned long long a) {
    asm("add.rn.f32x2 %0, %0, %1;" : "+l"(d) : "l"(a));
}
// XOR swizzle: stride-1 loads AND stride-4 staging stores both bank-conflict-free.
__device__ __forceinline__ int swz(int g) { return g ^ ((g >> 4) & 3); }

extern __shared__ unsigned long long s_u64[];   // r pairs: KP*NG u64 = 128 KB

__global__ __launch_bounds__(TPB, 1)
void conv_decoder_fused(const float* __restrict__ r,
                        const float* __restrict__ xc,
                        const float* __restrict__ xt,
                        const float* __restrict__ sigma,
                        const float* __restrict__ W,
                        const float* __restrict__ bias,
                        float* __restrict__ out) {
    unsigned long long* r2_s = s_u64;                       // [KP][NG]
    float* W_s = (float*)(s_u64 + KP * NG);                 // CIN*COUT

    __shared__ float s_mn[NWARP], s_mx[NWARP], s_sq[CIN];

    const int b    = blockIdx.y;
    const int tid  = threadIdx.x;
    const int warp = tid >> 5;
    const int lane = tid & 31;

    // ---- Phase A (one __syncthreads total) ------------------------------
    // A1: per-thread min/max over x_context and x_target, warp-reduced.
    {
        float mn = 1e30f, mx = -1e30f;
        for (int i = tid; i < NB * NCTX; i += TPB) {
            float v = xc[i]; mn = fminf(mn, v); mx = fmaxf(mx, v);
        }
        for (int i = tid; i < NB * NOUT; i += TPB) {
            float v = xt[i]; mn = fminf(mn, v); mx = fmaxf(mx, v);
        }
        #pragma unroll
        for (int s = 16; s > 0; s >>= 1) {
            mn = fminf(mn, __shfl_xor_sync(0xFFFFFFFFu, mn, s));
            mx = fmaxf(mx, __shfl_xor_sync(0xFFFFFFFFu, mx, s));
        }
        if (lane == 0) { s_mn[warp] = mn; s_mx[warp] = mx; }
    }
    // A2: exp2 prescales  exp(-0.5 d^2/s^2) = exp2(-(d*sq)^2), sq = sqrt(0.5*log2e)/s
    if (tid < CIN) s_sq[tid] = 0.84932180028801907f * expf(-sigma[tid]);
    // A3: weight matrix to smem.
    for (int i = tid; i < CIN * COUT; i += TPB) W_s[i] = W[i];
    // A4: stage r[b] as channel pairs, swizzled. 32x LDG.128 + 128x STS.64.
    {
        const float4* rb4 = (const float4*)(r + (size_t)b * CIN * NG);
        #pragma unroll
        for (int k = 0; k < KP; k++) {
            #pragma unroll
            for (int j = tid; j < NG / 4; j += TPB) {       // 2 iterations
                float4 a = rb4[(2 * k + 0) * (NG / 4) + j];
                float4 c = rb4[(2 * k + 1) * (NG / 4) + j];
                int g0 = 4 * j;
                r2_s[k * NG + swz(g0 + 0)] = pack2(a.x, c.x);
                r2_s[k * NG + swz(g0 + 1)] = pack2(a.y, c.y);
                r2_s[k * NG + swz(g0 + 2)] = pack2(a.z, c.z);
                r2_s[k * NG + swz(g0 + 3)] = pack2(a.w, c.w);
            }
        }
    }
    __syncthreads();

    // ---- Phase B: every thread finishes the tiny reductions locally -----
    float mn = s_mn[0], mx = s_mx[0];
    #pragma unroll
    for (int w = 1; w < NWARP; w++) {
        mn = fminf(mn, s_mn[w]); mx = fmaxf(mx, s_mx[w]);
    }
    const float xmin = mn - 0.1f;
    const float step = (mx + 0.1f - xmin) / (float)(NG - 1);

    bool uniform = true;
    #pragma unroll
    for (int c = 1; c < CIN; c++) uniform &= (s_sq[c] == s_sq[0]);

    const int o0 = blockIdx.x * TGT_BLK + warp * TGT;

    if (uniform) {
        const float sq    = s_sq[0];
        const float stepq = step * sq;
        const float baseq = xmin * sq;

        float xq[TGT];
        #pragma unroll
        for (int t = 0; t < TGT; t++) xq[t] = xt[b * NOUT + o0 + t] * sq;

        unsigned long long acc[TGT][KP];
        #pragma unroll
        for (int t = 0; t < TGT; t++)
            #pragma unroll
            for (int k = 0; k < KP; k++) acc[t][k] = 0ull;

        for (int i = lane; i < NG; i += 32) {
            const unsigned long long* rp = r2_s + swz(i);
            unsigned long long rv[KP];
            #pragma unroll
            for (int k = 0; k < KP; k++) rv[k] = rp[k * NG];

            float gq = fmaf((float)i, stepq, baseq);
            unsigned long long w2[TGT];
            #pragma unroll
            for (int t = 0; t < TGT; t++) {
                float d = gq - xq[t];
                float w = ex2(d * -d);
                w2[t] = pack2(w, w);
            }
            #pragma unroll
            for (int t = 0; t < TGT; t++)
                #pragma unroll
                for (int k = 0; k < KP; k++)
                    fma2(acc[t][k], rv[k], w2[t]);
        }

        #pragma unroll
        for (int s = 16; s > 0; s >>= 1)
            #pragma unroll
            for (int t = 0; t < TGT; t++)
                #pragma unroll
                for (int k = 0; k < KP; k++)
                    add2(acc[t][k], __shfl_xor_sync(0xFFFFFFFFu, acc[t][k], s));

        #pragma unroll
        for (int t = 0; t < TGT; t++) {
            float o = bias[lane];
            #pragma unroll
            for (int k = 0; k < KP; k++) {
                float lo, hi;
                unpack2(acc[t][k], lo, hi);
                o = fmaf(lo, W_s[(2 * k + 0) * COUT + lane], o);
                o = fmaf(hi, W_s[(2 * k + 1) * COUT + lane], o);
            }
            out[(size_t)(b * NOUT + o0 + t) * COUT + lane] = o;
        }
    } else {
        // General per-channel length scales (cold, scalar).
        float kneg[CIN];
        #pragma unroll
        for (int c = 0; c < CIN; c++) { float s = s_sq[c]; kneg[c] = -(s * s); }

        float xv[TGT];
        #pragma unroll
        for (int t = 0; t < TGT; t++) xv[t] = xt[b * NOUT + o0 + t];

        float acc[TGT][CIN];
        #pragma unroll
        for (int t = 0; t < TGT; t++)
            #pragma unroll
            for (int c = 0; c < CIN; c++) acc[t][c] = 0.0f;

        for (int i = lane; i < NG; i += 32) {
            const unsigned long long* rp = r2_s + swz(i);
            float rc[CIN];
            #pragma unroll
            for (int k = 0; k < KP; k++) unpack2(rp[k * NG], rc[2 * k], rc[2 * k + 1]);
            float gv = fmaf((float)i, step, xmin);
            #pragma unroll
            for (int t = 0; t < TGT; t++) {
                float d = gv - xv[t];
                float d2 = d * d;
                #pragma unroll
                for (int c = 0; c < CIN; c++)
                    acc[t][c] = fmaf(rc[c], ex2(d2 * kneg[c]), acc[t][c]);
            }
        }
        #pragma unroll
        for (int s = 16; s > 0; s >>= 1)
            #pragma unroll
            for (int t = 0; t < TGT; t++)
                #pragma unroll
                for (int c = 0; c < CIN; c++)
                    acc[t][c] += __shfl_xor_sync(0xFFFFFFFFu, acc[t][c], s);
        #pragma unroll
        for (int t = 0; t < TGT; t++) {
            float o = bias[lane];
            #pragma unroll
            for (int c = 0; c < CIN; c++)
                o = fmaf(acc[t][c], W_s[c * COUT + lane], o);
            out[(size_t)(b * NOUT + o0 + t) * COUT + lane] = o;
        }
    }
}

extern "C" void kernel_launch(void* const* d_in, const int* in_sizes, int n_in,
                              void* d_out, int out_size) {
    const float* r     = (const float*)d_in[0];
    const float* xc    = (const float*)d_in[1];
    // d_in[2] = y_context — unused by the reference computation.
    const float* xt    = (const float*)d_in[3];
    const float* sigma = (const float*)d_in[4];
    const float* W     = (const float*)d_in[5];
    const float* bias  = (const float*)d_in[6];
    float* out = (float*)d_out;

    (void)in_sizes; (void)n_in; (void)out_size;

    const int smem_bytes = KP * NG * 8 + CIN * COUT * 4;   // 128KB + 2KB
    cudaFuncSetAttribute(conv_decoder_fused,
                         cudaFuncAttributeMaxDynamicSharedMemorySize, smem_bytes);

    dim3 grid(NOUT / TGT_BLK, NB);   // (32, 4) = 128 blocks, 1 per SM
    conv_decoder_fused<<<grid, TPB, smem_bytes>>>(r, xc, xt, sigma, W, bias, out);
}

// round 5
// speedup vs baseline: 1.3287x; 1.0415x over previous
#include <cuda_runtime.h>

#define NG   2048
#define NB   4
#define CIN  16
#define COUT 32
#define NCTX 256
#define NOUT 1024

#define TPB   512
#define NWARP 16
#define TGT   4                    // targets per warp
#define TGT_BLK 32                 // 8 target-groups * 4 targets
#define KP   (CIN / 2)             // 8 channel pairs
#define HALFPTS (NG / 2)           // grid points per warp-half

__device__ __forceinline__ float ex2(float x) {
    float y;
    asm("ex2.approx.ftz.f32 %0, %1;" : "=f"(y) : "f"(x));
    return y;
}
__device__ __forceinline__ unsigned long long pack2(float lo, float hi) {
    unsigned long long v;
    asm("mov.b64 %0, {%1, %2};" : "=l"(v) : "f"(lo), "f"(hi));
    return v;
}
__device__ __forceinline__ void unpack2(unsigned long long v, float& lo, float& hi) {
    asm("mov.b64 {%0, %1}, %2;" : "=f"(lo), "=f"(hi) : "l"(v));
}
__device__ __forceinline__ void fma2(unsigned long long& d, unsigned long long a, unsigned long long b) {
    asm("fma.rn.f32x2 %0, %1, %2, %0;" : "+l"(d) : "l"(a), "l"(b));
}
__device__ __forceinline__ void add2(unsigned long long& d, unsigned long long a) {
    asm("add.rn.f32x2 %0, %0, %1;" : "+l"(d) : "l"(a));
}
// XOR swizzle: conflict-free for both the stride-4 staging stores and the
// stride-1 inner-loop loads.
__device__ __forceinline__ int swz(int g) { return g ^ ((g >> 4) & 3); }

extern __shared__ unsigned long long s_u64[];    // r pairs [KP][NG]: 128 KB

__global__ __launch_bounds__(TPB, 1)
void conv_decoder_fused(const float* __restrict__ r,
                        const float* __restrict__ xc,
                        const float* __restrict__ xt,
                        const float* __restrict__ sigma,
                        const float* __restrict__ W,
                        const float* __restrict__ bias,
                        float* __restrict__ out) {
    unsigned long long* r2_s = s_u64;                 // [KP][NG]
    float* W_s = (float*)(s_u64 + KP * NG);           // CIN*COUT

    __shared__ float s_mn[NWARP], s_mx[NWARP], s_sq[CIN];
    __shared__ float s_red[TGT_BLK][COUT];            // half-1 projected partials

    const int b    = blockIdx.y;
    const int tid  = threadIdx.x;
    const int warp = tid >> 5;
    const int lane = tid & 31;
    const int wt   = warp & 7;       // target-group within block
    const int hs   = warp >> 3;      // grid half this warp sums

    // ---- Phase A: prep + staging (one __syncthreads) ---------------------
    {
        float mn = 1e30f, mx = -1e30f;
        for (int i = tid; i < NB * NCTX; i += TPB) {
            float v = xc[i]; mn = fminf(mn, v); mx = fmaxf(mx, v);
        }
        for (int i = tid; i < NB * NOUT; i += TPB) {
            float v = xt[i]; mn = fminf(mn, v); mx = fmaxf(mx, v);
        }
        #pragma unroll
        for (int s = 16; s > 0; s >>= 1) {
            mn = fminf(mn, __shfl_xor_sync(0xFFFFFFFFu, mn, s));
            mx = fmaxf(mx, __shfl_xor_sync(0xFFFFFFFFu, mx, s));
        }
        if (lane == 0) { s_mn[warp] = mn; s_mx[warp] = mx; }
    }
    // exp(-0.5 d^2/s^2) = exp2(-(d*sq)^2),  sq = sqrt(0.5*log2(e)) / s
    if (tid < CIN) s_sq[tid] = 0.84932180028801907f * expf(-sigma[tid]);
    for (int i = tid; i < CIN * COUT; i += TPB) W_s[i] = W[i];
    {
        const float4* rb4 = (const float4*)(r + (size_t)b * CIN * NG);
        #pragma unroll
        for (int k = 0; k < KP; k++) {
            int j = tid;                               // NG/4 == TPB: one shot
            float4 a = rb4[(2 * k + 0) * (NG / 4) + j];
            float4 c = rb4[(2 * k + 1) * (NG / 4) + j];
            int g0 = 4 * j;
            r2_s[k * NG + swz(g0 + 0)] = pack2(a.x, c.x);
            r2_s[k * NG + swz(g0 + 1)] = pack2(a.y, c.y);
            r2_s[k * NG + swz(g0 + 2)] = pack2(a.z, c.z);
            r2_s[k * NG + swz(g0 + 3)] = pack2(a.w, c.w);
        }
    }
    __syncthreads();

    float mn = s_mn[0], mx = s_mx[0];
    #pragma unroll
    for (int w = 1; w < NWARP; w++) {
        mn = fminf(mn, s_mn[w]); mx = fmaxf(mx, s_mx[w]);
    }
    const float xmin = mn - 0.1f;
    const float step = (mx + 0.1f - xmin) / (float)(NG - 1);

    bool uniform = true;
    #pragma unroll
    for (int c = 1; c < CIN; c++) uniform &= (s_sq[c] == s_sq[0]);

    const int o0 = blockIdx.x * TGT_BLK + wt * TGT;
    const int gbase = hs * HALFPTS + lane;

    float op[TGT];   // this lane's projected output-channel value per target

    if (uniform) {
        const float sq    = s_sq[0];
        const float stepq = step * sq;
        const float dstep = 32.0f * stepq;

        // d_t = (xmin + g*step - x_t)*sq, advanced incrementally.
        float d[TGT];
        #pragma unroll
        for (int t = 0; t < TGT; t++)
            d[t] = fmaf((float)gbase, stepq, xmin * sq) - xt[b * NOUT + o0 + t] * sq;

        unsigned long long acc[TGT][KP];
        #pragma unroll
        for (int t = 0; t < TGT; t++)
            #pragma unroll
            for (int k = 0; k < KP; k++) acc[t][k] = 0ull;

        #pragma unroll 2
        for (int it = 0; it < HALFPTS / 32; it++) {
            const unsigned long long* rp = r2_s + swz(gbase + it * 32);
            unsigned long long rv[KP];
            #pragma unroll
            for (int k = 0; k < KP; k++) rv[k] = rp[k * NG];

            unsigned long long w2[TGT];
            #pragma unroll
            for (int t = 0; t < TGT; t++) {
                float w = ex2(d[t] * -d[t]);
                d[t] += dstep;
                w2[t] = pack2(w, w);
            }
            #pragma unroll
            for (int t = 0; t < TGT; t++)
                #pragma unroll
                for (int k = 0; k < KP; k++)
                    fma2(acc[t][k], rv[k], w2[t]);
        }

        // CORRECT tail order: reduce the packed accumulators across lanes
        // first (every lane ends with full channel sums), THEN project.
        #pragma unroll
        for (int s = 16; s > 0; s >>= 1)
            #pragma unroll
            for (int t = 0; t < TGT; t++)
                #pragma unroll
                for (int k = 0; k < KP; k++)
                    add2(acc[t][k], __shfl_xor_sync(0xFFFFFFFFu, acc[t][k], s));

        #pragma unroll
        for (int t = 0; t < TGT; t++) {
            float o = 0.0f;
            #pragma unroll
            for (int k = 0; k < KP; k++) {
                float lo, hi;
                unpack2(acc[t][k], lo, hi);
                o = fmaf(lo, W_s[(2 * k + 0) * COUT + lane], o);
                o = fmaf(hi, W_s[(2 * k + 1) * COUT + lane], o);
            }
            op[t] = o;
        }
    } else {
        // Cold path: per-channel length scales (scalar math).
        float kneg[CIN];
        #pragma unroll
        for (int c = 0; c < CIN; c++) { float s = s_sq[c]; kneg[c] = -(s * s); }

        float xv[TGT];
        #pragma unroll
        for (int t = 0; t < TGT; t++) xv[t] = xt[b * NOUT + o0 + t];

        float acc[TGT][CIN];
        #pragma unroll
        for (int t = 0; t < TGT; t++)
            #pragma unroll
            for (int c = 0; c < CIN; c++) acc[t][c] = 0.0f;

        for (int it = 0; it < HALFPTS / 32; it++) {
            int i = gbase + it * 32;
            const unsigned long long* rp = r2_s + swz(i);
            float rc[CIN];
            #pragma unroll
            for (int k = 0; k < KP; k++) unpack2(rp[k * NG], rc[2 * k], rc[2 * k + 1]);
            float gv = fmaf((float)i, step, xmin);
            #pragma unroll
            for (int t = 0; t < TGT; t++) {
                float dd = gv - xv[t];
                float d2 = dd * dd;
                #pragma unroll
                for (int c = 0; c < CIN; c++)
                    acc[t][c] = fmaf(rc[c], ex2(d2 * kneg[c]), acc[t][c]);
            }
        }
        // Reduce first, then project (same fix as hot path).
        #pragma unroll
        for (int s = 16; s > 0; s >>= 1)
            #pragma unroll
            for (int t = 0; t < TGT; t++)
                #pragma unroll
                for (int c = 0; c < CIN; c++)
                    acc[t][c] += __shfl_xor_sync(0xFFFFFFFFu, acc[t][c], s);
        #pragma unroll
        for (int t = 0; t < TGT; t++) {
            float o = 0.0f;
            #pragma unroll
            for (int c = 0; c < CIN; c++)
                o = fmaf(acc[t][c], W_s[c * COUT + lane], o);
            op[t] = o;
        }
    }

    // ---- Cross-half combine inside the block -----------------------------
    if (hs == 1) {
        #pragma unroll
        for (int t = 0; t < TGT; t++) s_red[wt * TGT + t][lane] = op[t];
    }
    __syncthreads();
    if (hs == 0) {
        const float bv = bias[lane];
        #pragma unroll
        for (int t = 0; t < TGT; t++)
            out[(size_t)(b * NOUT + o0 + t) * COUT + lane] =
                op[t] + s_red[wt * TGT + t][lane] + bv;
    }
}

extern "C" void kernel_launch(void* const* d_in, const int* in_sizes, int n_in,
                              void* d_out, int out_size) {
    const float* r     = (const float*)d_in[0];
    const float* xc    = (const float*)d_in[1];
    // d_in[2] = y_context — unused by the reference computation.
    const float* xt    = (const float*)d_in[3];
    const float* sigma = (const float*)d_in[4];
    const float* W     = (const float*)d_in[5];
    const float* bias  = (const float*)d_in[6];
    float* out = (float*)d_out;

    (void)in_sizes; (void)n_in; (void)out_size;

    const int smem_bytes = KP * NG * 8 + CIN * COUT * 4;   // 128KB + 2KB dynamic
    cudaFuncSetAttribute(conv_decoder_fused,
                         cudaFuncAttributeMaxDynamicSharedMemorySize, smem_bytes);

    dim3 grid(NOUT / TGT_BLK, NB);   // (32, 4) = 128 blocks, 1 per SM
    conv_decoder_fused<<<grid, TPB, smem_bytes>>>(r, xc, xt, sigma, W, bias, out);
}

// round 6
// speedup vs baseline: 1.3310x; 1.0017x over previous
#include <cuda_runtime.h>

#define NG   2048
#define NB   4
#define CIN  16
#define COUT 32
#define NCTX 256
#define NOUT 1024

#define TPB   512
#define NWARP 16
#define TGT   4                    // targets per warp
#define TGT_BLK 32                 // 8 target-groups * 4 targets
#define KP   (CIN / 2)             // 8 channel pairs
#define HALFPTS (NG / 2)           // grid points per warp-half

__device__ __forceinline__ float ex2(float x) {
    float y;
    asm("ex2.approx.ftz.f32 %0, %1;" : "=f"(y) : "f"(x));
    return y;
}
__device__ __forceinline__ unsigned long long pack2(float lo, float hi) {
    unsigned long long v;
    asm("mov.b64 %0, {%1, %2};" : "=l"(v) : "f"(lo), "f"(hi));
    return v;
}
__device__ __forceinline__ void unpack2(unsigned long long v, float& lo, float& hi) {
    asm("mov.b64 {%0, %1}, %2;" : "=f"(lo), "=f"(hi) : "l"(v));
}
__device__ __forceinline__ void fma2(unsigned long long& d, unsigned long long a, unsigned long long b) {
    asm("fma.rn.f32x2 %0, %1, %2, %0;" : "+l"(d) : "l"(a), "l"(b));
}
__device__ __forceinline__ void add2(unsigned long long& d, unsigned long long a) {
    asm("add.rn.f32x2 %0, %0, %1;" : "+l"(d) : "l"(a));
}
// XOR swizzle: conflict-free for both the stride-4 staging stores and the
// stride-1 inner-loop loads.
__device__ __forceinline__ int swz(int g) { return g ^ ((g >> 4) & 3); }

extern __shared__ unsigned long long s_u64[];    // r pairs [KP][NG]: 128 KB

__global__ __launch_bounds__(TPB, 1)
void conv_decoder_fused(const float* __restrict__ r,
                        const float* __restrict__ xc,
                        const float* __restrict__ xt,
                        const float* __restrict__ sigma,
                        const float* __restrict__ W,
                        const float* __restrict__ bias,
                        float* __restrict__ out) {
    unsigned long long* r2_s = s_u64;                 // [KP][NG]
    float* W_s = (float*)(s_u64 + KP * NG);           // CIN*COUT

    __shared__ float s_mn[NWARP], s_mx[NWARP], s_sq[CIN];
    __shared__ float s_red[TGT_BLK][COUT];            // half-1 projected partials

    const int b    = blockIdx.y;
    const int tid  = threadIdx.x;
    const int warp = tid >> 5;
    const int lane = tid & 31;
    const int wt   = warp & 7;       // target-group within block
    const int hs   = warp >> 3;      // grid half this warp sums

    // ---- Phase A: prep + staging (one __syncthreads) ---------------------
    {
        float mn = 1e30f, mx = -1e30f;
        for (int i = tid; i < NB * NCTX; i += TPB) {
            float v = xc[i]; mn = fminf(mn, v); mx = fmaxf(mx, v);
        }
        for (int i = tid; i < NB * NOUT; i += TPB) {
            float v = xt[i]; mn = fminf(mn, v); mx = fmaxf(mx, v);
        }
        #pragma unroll
        for (int s = 16; s > 0; s >>= 1) {
            mn = fminf(mn, __shfl_xor_sync(0xFFFFFFFFu, mn, s));
            mx = fmaxf(mx, __shfl_xor_sync(0xFFFFFFFFu, mx, s));
        }
        if (lane == 0) { s_mn[warp] = mn; s_mx[warp] = mx; }
    }
    // exp(-0.5 d^2/s^2) = exp2(-(d*sq)^2),  sq = sqrt(0.5*log2(e)) / s
    if (tid < CIN) s_sq[tid] = 0.84932180028801907f * expf(-sigma[tid]);
    for (int i = tid; i < CIN * COUT; i += TPB) W_s[i] = W[i];
    {
        const float4* rb4 = (const float4*)(r + (size_t)b * CIN * NG);
        #pragma unroll
        for (int k = 0; k < KP; k++) {
            int j = tid;                               // NG/4 == TPB: one shot
            float4 a = rb4[(2 * k + 0) * (NG / 4) + j];
            float4 c = rb4[(2 * k + 1) * (NG / 4) + j];
            int g0 = 4 * j;
            r2_s[k * NG + swz(g0 + 0)] = pack2(a.x, c.x);
            r2_s[k * NG + swz(g0 + 1)] = pack2(a.y, c.y);
            r2_s[k * NG + swz(g0 + 2)] = pack2(a.z, c.z);
            r2_s[k * NG + swz(g0 + 3)] = pack2(a.w, c.w);
        }
    }
    __syncthreads();

    float mn = s_mn[0], mx = s_mx[0];
    #pragma unroll
    for (int w = 1; w < NWARP; w++) {
        mn = fminf(mn, s_mn[w]); mx = fmaxf(mx, s_mx[w]);
    }
    const float xmin = mn - 0.1f;
    const float step = (mx + 0.1f - xmin) / (float)(NG - 1);

    bool uniform = true;
    #pragma unroll
    for (int c = 1; c < CIN; c++) uniform &= (s_sq[c] == s_sq[0]);

    const int o0 = blockIdx.x * TGT_BLK + wt * TGT;
    const int gbase = hs * HALFPTS + lane;

    float op[TGT];   // this lane's projected output-channel value per target

    if (uniform) {
        const float sq    = s_sq[0];
        const float stepq = step * sq;
        const float dstep = 32.0f * stepq;

        // d_t = (xmin + g*step - x_t)*sq, advanced incrementally.
        float d[TGT];
        #pragma unroll
        for (int t = 0; t < TGT; t++)
            d[t] = fmaf((float)gbase, stepq, xmin * sq) - xt[b * NOUT + o0 + t] * sq;

        unsigned long long acc[TGT][KP];
        #pragma unroll
        for (int t = 0; t < TGT; t++)
            #pragma unroll
            for (int k = 0; k < KP; k++) acc[t][k] = 0ull;

        #pragma unroll 1
        for (int it = 0; it < HALFPTS / 32; it++) {
            const unsigned long long* rp = r2_s + swz(gbase + it * 32);

            unsigned long long w2[TGT];
            #pragma unroll
            for (int t = 0; t < TGT; t++) {
                float w = ex2(d[t] * -d[t]);
                d[t] += dstep;
                w2[t] = pack2(w, w);
            }
            // Channel pairs in two groups of 4: halves the live rv set,
            // keeping total live regs ~100 (no spills at the 128-reg cap).
            {
                unsigned long long rv[4];
                #pragma unroll
                for (int k = 0; k < 4; k++) rv[k] = rp[k * NG];
                #pragma unroll
                for (int t = 0; t < TGT; t++)
                    #pragma unroll
                    for (int k = 0; k < 4; k++)
                        fma2(acc[t][k], rv[k], w2[t]);
            }
            {
                unsigned long long rv[4];
                #pragma unroll
                for (int k = 0; k < 4; k++) rv[k] = rp[(k + 4) * NG];
                #pragma unroll
                for (int t = 0; t < TGT; t++)
                    #pragma unroll
                    for (int k = 0; k < 4; k++)
                        fma2(acc[t][k + 4], rv[k], w2[t]);
            }
        }

        // Reduce packed accumulators across lanes first, THEN project.
        #pragma unroll
        for (int s = 16; s > 0; s >>= 1)
            #pragma unroll
            for (int t = 0; t < TGT; t++)
                #pragma unroll
                for (int k = 0; k < KP; k++)
                    add2(acc[t][k], __shfl_xor_sync(0xFFFFFFFFu, acc[t][k], s));

        #pragma unroll
        for (int t = 0; t < TGT; t++) {
            float o = 0.0f;
            #pragma unroll
            for (int k = 0; k < KP; k++) {
                float lo, hi;
                unpack2(acc[t][k], lo, hi);
                o = fmaf(lo, W_s[(2 * k + 0) * COUT + lane], o);
                o = fmaf(hi, W_s[(2 * k + 1) * COUT + lane], o);
            }
            op[t] = o;
        }
    } else {
        // Cold path: per-channel length scales (scalar math).
        float kneg[CIN];
        #pragma unroll
        for (int c = 0; c < CIN; c++) { float s = s_sq[c]; kneg[c] = -(s * s); }

        float xv[TGT];
        #pragma unroll
        for (int t = 0; t < TGT; t++) xv[t] = xt[b * NOUT + o0 + t];

        float acc[TGT][CIN];
        #pragma unroll
        for (int t = 0; t < TGT; t++)
            #pragma unroll
            for (int c = 0; c < CIN; c++) acc[t][c] = 0.0f;

        #pragma unroll 1
        for (int it = 0; it < HALFPTS / 32; it++) {
            int i = gbase + it * 32;
            const unsigned long long* rp = r2_s + swz(i);
            float gv = fmaf((float)i, step, xmin);
            #pragma unroll
            for (int k = 0; k < KP; k++) {
                float rlo, rhi;
                unpack2(rp[k * NG], rlo, rhi);
                #pragma unroll
                for (int t = 0; t < TGT; t++) {
                    float dd = gv - xv[t];
                    float d2 = dd * dd;
                    acc[t][2 * k + 0] = fmaf(rlo, ex2(d2 * kneg[2 * k + 0]), acc[t][2 * k + 0]);
                    acc[t][2 * k + 1] = fmaf(rhi, ex2(d2 * kneg[2 * k + 1]), acc[t][2 * k + 1]);
                }
            }
        }
        // Reduce first, then project.
        #pragma unroll
        for (int s = 16; s > 0; s >>= 1)
            #pragma unroll
            for (int t = 0; t < TGT; t++)
                #pragma unroll
                for (int c = 0; c < CIN; c++)
                    acc[t][c] += __shfl_xor_sync(0xFFFFFFFFu, acc[t][c], s);
        #pragma unroll
        for (int t = 0; t < TGT; t++) {
            float o = 0.0f;
            #pragma unroll
            for (int c = 0; c < CIN; c++)
                o = fmaf(acc[t][c], W_s[c * COUT + lane], o);
            op[t] = o;
        }
    }

    // ---- Cross-half combine inside the block -----------------------------
    if (hs == 1) {
        #pragma unroll
        for (int t = 0; t < TGT; t++) s_red[wt * TGT + t][lane] = op[t];
    }
    __syncthreads();
    if (hs == 0) {
        const float bv = bias[lane];
        #pragma unroll
        for (int t = 0; t < TGT; t++)
            out[(size_t)(b * NOUT + o0 + t) * COUT + lane] =
                op[t] + s_red[wt * TGT + t][lane] + bv;
    }
}

extern "C" void kernel_launch(void* const* d_in, const int* in_sizes, int n_in,
                              void* d_out, int out_size) {
    const float* r     = (const float*)d_in[0];
    const float* xc    = (const float*)d_in[1];
    // d_in[2] = y_context — unused by the reference computation.
    const float* xt    = (const float*)d_in[3];
    const float* sigma = (const float*)d_in[4];
    const float* W     = (const float*)d_in[5];
    const float* bias  = (const float*)d_in[6];
    float* out = (float*)d_out;

    (void)in_sizes; (void)n_in; (void)out_size;

    const int smem_bytes = KP * NG * 8 + CIN * COUT * 4;   // 128KB + 2KB dynamic
    cudaFuncSetAttribute(conv_decoder_fused,
                         cudaFuncAttributeMaxDynamicSharedMemorySize, smem_bytes);

    dim3 grid(NOUT / TGT_BLK, NB);   // (32, 4) = 128 blocks, 1 per SM
    conv_decoder_fused<<<grid, TPB, smem_bytes>>>(r, xc, xt, sigma, W, bias, out);
}